// round 14
// baseline (speedup 1.0000x reference)
#include <cuda_runtime.h>
#include <cuda_bf16.h>

// DWT_1D via polyphase, software-pipelined halves.
//   lo[k] = h0*xo[k-2]+h2*xo[k-1]+h4*xo[k]+h6*xo[k+1]
//         + h1*xe[k-1]+h3*xe[k]+h5*xe[k+1]+h7*xe[k+2]
//   hi[k] = h7*xo[k-2]+h5*xo[k-1]+h3*xo[k]+h1*xo[k+1]
//         - h6*xe[k-1]-h4*xe[k]-h2*xe[k+1]-h0*xe[k+2]
// (REC_HI[j] = (-1)^j REC_LO[7-j] bit-exact -> hi reuses the lo taps.)
// One block per row; half1's global loads are issued before computing half0,
// so half1's memory latency is hidden behind half0's compute.

namespace {
constexpr int SEQ  = 8192;
constexpr int KOUT = 4096;
constexpr int NC   = 16 * 64;     // 1024 rows
constexpr int TPB  = 256;
constexpr int KH   = KOUT / 2;    // 2048 outputs per half
constexpr int NQ   = 1028;        // float4 slots per half (incl. halo)
constexpr int NP   = 2 * NQ;      // floats per phase per half (2056)
constexpr int S4   = SEQ / 4;     // 2048 float4 per row
}

__device__ __forceinline__ void compute_half(
    const float* __restrict__ pe_s, const float* __restrict__ po_s,
    const float* __restrict__ h, int tid,
    float4* __restrict__ lo4, float4* __restrict__ hi4)
{
    const float4* __restrict__ pe4 = reinterpret_cast<const float4*>(pe_s);
    const float4* __restrict__ po4 = reinterpret_cast<const float4*>(po_s);
    #pragma unroll
    for (int it = 0; it < KH / 4 / TPB; ++it) {      // 2 iters
        const int t = tid + it * TPB;                // outputs k = K0+4t..+3
        float4 o0 = po4[t];
        float4 o1 = po4[t + 1];
        float4 e0 = pe4[t];
        float4 e1 = pe4[t + 1];
        const float o[8] = { o0.x, o0.y, o0.z, o0.w, o1.x, o1.y, o1.z, o1.w };
        const float e[8] = { e0.x, e0.y, e0.z, e0.w, e1.x, e1.y, e1.z, e1.w };

        float lo[4], hi[4];
        #pragma unroll
        for (int d = 0; d < 4; ++d) {
            float s0 = fmaf(h[0], o[d+0], h[1] * e[d+1]);
            s0 = fmaf(h[2], o[d+1], s0);
            s0 = fmaf(h[3], e[d+2], s0);
            s0 = fmaf(h[4], o[d+2], s0);
            s0 = fmaf(h[5], e[d+3], s0);
            s0 = fmaf(h[6], o[d+3], s0);
            s0 = fmaf(h[7], e[d+4], s0);
            lo[d] = s0;

            float s1 = fmaf(h[7], o[d+0], h[6] * (-e[d+1]));
            s1 = fmaf(h[5], o[d+1], s1);
            s1 = fmaf(h[4], -e[d+2], s1);
            s1 = fmaf(h[3], o[d+2], s1);
            s1 = fmaf(h[2], -e[d+3], s1);
            s1 = fmaf(h[1], o[d+3], s1);
            s1 = fmaf(h[0], -e[d+4], s1);
            hi[d] = s1;
        }
        lo4[t] = make_float4(lo[0], lo[1], lo[2], lo[3]);
        hi4[t] = make_float4(hi[0], hi[1], hi[2], hi[3]);
    }
}

__global__ __launch_bounds__(TPB, 4)
void dwt1d_kernel(const float4* __restrict__ x4,
                  const float* __restrict__ mlo,
                  const float* __restrict__ mhi,
                  float* __restrict__ out)
{
    // pe_s[h][j] = xe[h*KH - 2 + j], po_s[h][j] = xo[h*KH - 2 + j]
    __shared__ alignas(16) float pe_s[2][NP];
    __shared__ alignas(16) float po_s[2][NP];

    const int row = blockIdx.x;
    const int tid = threadIdx.x;
    const float4* __restrict__ xr = x4 + (size_t)row * S4;

    const float4 z = make_float4(0.f, 0.f, 0.f, 0.f);

    // ---- Load half0 (f = q - 1, q = 0..1027) ----
    float4 a[5];
    #pragma unroll
    for (int i = 0; i < 5; ++i) {
        const int q = tid + i * TPB;
        const int f = q - 1;
        a[i] = ((i < 4 || q < NQ) && f >= 0) ? xr[f] : z;
    }
    // STS half0 (deinterleave)
    {
        float2* __restrict__ pe2 = reinterpret_cast<float2*>(pe_s[0]);
        float2* __restrict__ po2 = reinterpret_cast<float2*>(po_s[0]);
        #pragma unroll
        for (int i = 0; i < 5; ++i) {
            const int q = tid + i * TPB;
            if (i < 4 || q < NQ) {
                pe2[q] = make_float2(a[i].x, a[i].z);
                po2[q] = make_float2(a[i].y, a[i].w);
            }
        }
    }

    // ---- Issue loads for half1 (f = 1023 + q) — latency hidden behind compute0 ----
    float4 b[5];
    #pragma unroll
    for (int i = 0; i < 5; ++i) {
        const int q = tid + i * TPB;
        const int f = KH / 2 - 1 + q;
        b[i] = ((i < 4 || q < NQ) && f < S4) ? xr[f] : z;
    }

    // Low-pass taps (hi derived); row 2, cols 1..8 of the banded matrix.
    float h[8];
    #pragma unroll
    for (int j = 0; j < 8; ++j) h[j] = __ldg(&mlo[2 * SEQ + 1 + j]);

    __syncthreads();

    // ---- Compute half0 ----
    {
        float4* __restrict__ lo4 = reinterpret_cast<float4*>(out + (size_t)row * KOUT);
        float4* __restrict__ hi4 = reinterpret_cast<float4*>(out + (size_t)NC * KOUT + (size_t)row * KOUT);
        compute_half(pe_s[0], po_s[0], h, tid, lo4, hi4);
    }

    // ---- STS half1 (loads landed during compute0) ----
    {
        float2* __restrict__ pe2 = reinterpret_cast<float2*>(pe_s[1]);
        float2* __restrict__ po2 = reinterpret_cast<float2*>(po_s[1]);
        #pragma unroll
        for (int i = 0; i < 5; ++i) {
            const int q = tid + i * TPB;
            if (i < 4 || q < NQ) {
                pe2[q] = make_float2(b[i].x, b[i].z);
                po2[q] = make_float2(b[i].y, b[i].w);
            }
        }
    }

    __syncthreads();

    // ---- Compute half1 ----
    {
        float4* __restrict__ lo4 = reinterpret_cast<float4*>(out + (size_t)row * KOUT + KH);
        float4* __restrict__ hi4 = reinterpret_cast<float4*>(out + (size_t)NC * KOUT + (size_t)row * KOUT + KH);
        compute_half(pe_s[1], po_s[1], h, tid, lo4, hi4);
    }
}

extern "C" void kernel_launch(void* const* d_in, const int* in_sizes, int n_in,
                              void* d_out, int out_size)
{
    const float4* x  = (const float4*)d_in[0];
    const float* mlo = (const float*)d_in[1];
    const float* mhi = (const float*)d_in[2];
    float* out = (float*)d_out;

    dwt1d_kernel<<<NC, TPB>>>(x, mlo, mhi, out);
}

// round 17
// speedup vs baseline: 1.0251x; 1.0251x over previous
#include <cuda_runtime.h>
#include <cuda_bf16.h>

// DWT_1D, register-only streaming: no smem, no barriers, no phases.
// Thread u -> (row, f): owns input float4 f of the row, produces outputs
// k = 2f, 2f+1 for both bands.
//   lo[k] = sum_j h[j] * x[2k+j-3]
//   hi[k] = sum_j (-1)^j h[7-j] * x[2k+j-3]   (bit-exact vs REC_HI)
// Window for k=2f..2f+1 is x[4f-3 .. 4f+6] -> float4s f-1, f, f+1. All three
// LDG.128 are lane-dense (16B lane stride); the 3x read redundancy is
// L1/L2-absorbed. MLP_p1=3 keeps cross-CTA L1tex-queue spread at the floor
// (the fat staged blocks with MLP_p1~8-10 were the 12.5us plateau).

namespace {
constexpr int SEQ  = 8192;
constexpr int KOUT = 4096;
constexpr int NC   = 16 * 64;     // 1024 rows
constexpr int TPB  = 256;
constexpr int S4   = SEQ / 4;     // 2048 float4 per row
}

__global__ __launch_bounds__(TPB)
void dwt1d_kernel(const float4* __restrict__ x4,
                  const float* __restrict__ mlo,
                  const float* __restrict__ mhi,
                  float* __restrict__ out)
{
    const int u   = blockIdx.x * TPB + threadIdx.x;  // 0 .. NC*S4-1
    const int row = u >> 11;                         // / 2048
    const int f   = u & (S4 - 1);                    // float4 index in row

    const float4* __restrict__ xr = x4 + (size_t)row * S4;
    const float4 z = make_float4(0.f, 0.f, 0.f, 0.f);

    // Three dense, coalesced loads (predicated only at row edges).
    float4 vm = (f > 0)      ? xr[f - 1] : z;
    float4 v0 = xr[f];
    float4 vp = (f < S4 - 1) ? xr[f + 1] : z;

    // Low-pass taps from the banded matrix (row 2, cols 1..8); hi derived.
    float h[8];
    #pragma unroll
    for (int j = 0; j < 8; ++j) h[j] = __ldg(&mlo[2 * SEQ + 1 + j]);

    // w[m] = x[4f - 4 + m], m = 0..11
    const float w[12] = { vm.x, vm.y, vm.z, vm.w,
                          v0.x, v0.y, v0.z, v0.w,
                          vp.x, vp.y, vp.z, vp.w };

    // k = 2f + d (d = 0,1): x[2k+j-3] = w[2d + 1 + j]
    float lo0, lo1, hi0, hi1;
    {
        float s = h[0] * w[1];
        #pragma unroll
        for (int j = 1; j < 8; ++j) s = fmaf(h[j], w[1 + j], s);
        lo0 = s;
    }
    {
        float s = h[0] * w[3];
        #pragma unroll
        for (int j = 1; j < 8; ++j) s = fmaf(h[j], w[3 + j], s);
        lo1 = s;
    }
    {
        // hi taps: g[j] = (-1)^j * h[7-j]
        float s = h[7] * w[1];
        s = fmaf(-h[6], w[2], s);
        s = fmaf( h[5], w[3], s);
        s = fmaf(-h[4], w[4], s);
        s = fmaf( h[3], w[5], s);
        s = fmaf(-h[2], w[6], s);
        s = fmaf( h[1], w[7], s);
        s = fmaf(-h[0], w[8], s);
        hi0 = s;
    }
    {
        float s = h[7] * w[3];
        s = fmaf(-h[6], w[4], s);
        s = fmaf( h[5], w[5], s);
        s = fmaf(-h[4], w[6], s);
        s = fmaf( h[3], w[7], s);
        s = fmaf(-h[2], w[8], s);
        s = fmaf( h[1], w[9], s);
        s = fmaf(-h[0], w[10], s);
        hi1 = s;
    }

    float2* __restrict__ lo2 = reinterpret_cast<float2*>(out + (size_t)row * KOUT);
    float2* __restrict__ hi2 = reinterpret_cast<float2*>(out + (size_t)NC * KOUT + (size_t)row * KOUT);
    lo2[f] = make_float2(lo0, lo1);
    hi2[f] = make_float2(hi0, hi1);
}

extern "C" void kernel_launch(void* const* d_in, const int* in_sizes, int n_in,
                              void* d_out, int out_size)
{
    const float4* x  = (const float4*)d_in[0];
    const float* mlo = (const float*)d_in[1];
    const float* mhi = (const float*)d_in[2];
    float* out = (float*)d_out;

    dwt1d_kernel<<<(NC * S4) / TPB, TPB>>>(x, mlo, mhi, out);
}